// round 1
// baseline (speedup 1.0000x reference)
#include <cuda_runtime.h>

// Dendrite_755914244697 on sm_103a
// out[c,oy,ox,n] = sum_{i,j in 5x5} log(1.1 + atan(10*(x[c,oy+i,ox+j]*w[...] - q[...]))/pi)
//
// Layout facts:
//   x : (1,3,128,128) fp32, 49152 elems
//   w : (3,124,124,25,5,5) fp32, 28,830,000 elems  -> flat = o*25 + (i*5+j), o = output index
//   q : same as w
//   out: (1,3,124,124,25) fp32, 1,153,200 elems, n innermost -> flat o matches w/q segment
//
// Strategy: one thread per output. w/q segments (25 consecutive floats each) are
// staged into shared memory with fully coalesced float4 global loads; per-thread
// smem reads at tid*25+k are bank-conflict-free (stride 25, gcd(25,32)=1).
// x patch (25 values) held in registers; heavily L1-resident across blocks.

#define CHAN 3
#define IMG  128
#define OUTD 124
#define SIDE 5
#define SEG  25            // floats of w (and q) per output
#define TPB  224           // outputs (= threads) per block
#define SMEMF (TPB * SEG)  // 5600 floats per array -> 22.4 KB each, 44.8 KB total

__device__ __forceinline__ float fast_atan(float x)
{
    // atan via odd minimax poly on [0,1], degree 15; |x|>1 handled with
    // atan(x) = pi/2 - atan(1/x). Max abs error ~1e-7.
    float ax = fabsf(x);
    float inv;
    asm("rcp.approx.f32 %0, %1;" : "=f"(inv) : "f"(ax));
    bool  big = ax > 1.0f;
    float z   = big ? inv : ax;
    float s   = z * z;
    float p   =              -0.0040540580f;
    p = __fmaf_rn(p, s,  0.0218612288f);
    p = __fmaf_rn(p, s, -0.0559098861f);
    p = __fmaf_rn(p, s,  0.0964200441f);
    p = __fmaf_rn(p, s, -0.1390853351f);
    p = __fmaf_rn(p, s,  0.1994653599f);
    p = __fmaf_rn(p, s, -0.3332985605f);
    p = __fmaf_rn(p, s,  0.9999993329f);
    float r = p * z;
    if (big) r = 1.5707963268f - r;
    // copy sign of x onto r
    return __uint_as_float((__float_as_uint(r) & 0x7fffffffu) |
                           (__float_as_uint(x) & 0x80000000u));
}

__global__ void __launch_bounds__(TPB)
dendrite_kernel(const float* __restrict__ x,
                const float* __restrict__ w,
                const float* __restrict__ q,
                float*       __restrict__ out,
                int n_out, int n_wq)
{
    __shared__ float ws[SMEMF];
    __shared__ float qs[SMEMF];

    const int tid = threadIdx.x;

    // ---- Stage this block's w/q segments with coalesced float4 loads ----
    // Block base = blockIdx.x * 5600 floats = 22,400 bytes -> 16B aligned.
    {
        const int     total4 = n_wq >> 2;                 // 7,207,500
        const int     b4     = blockIdx.x * (SMEMF / 4);  // float4 base
        const float4* __restrict__ w4 = reinterpret_cast<const float4*>(w);
        const float4* __restrict__ q4 = reinterpret_cast<const float4*>(q);
        float4* ws4 = reinterpret_cast<float4*>(ws);
        float4* qs4 = reinterpret_cast<float4*>(qs);
        for (int i = tid; i < SMEMF / 4; i += TPB) {
            int g = b4 + i;
            if (g < total4) {
                ws4[i] = __ldg(w4 + g);
                qs4[i] = __ldg(q4 + g);
            }
        }
    }
    __syncthreads();

    const int o = blockIdx.x * TPB + tid;
    if (o >= n_out) return;

    // Decode spatial position: o = ((c*124 + oy)*124 + ox)*25 + n ; x doesn't depend on n.
    const int s  = o / 25;
    const int c  = s / (OUTD * OUTD);
    const int r  = s - c * (OUTD * OUTD);
    const int oy = r / OUTD;
    const int ox = r - oy * OUTD;

    // Load the 5x5 x-patch into registers (L1-resident, broadcast across lanes
    // that share the same spatial position).
    const float* __restrict__ xp = x + (c * IMG + oy) * IMG + ox;
    float pv[SEG];
#pragma unroll
    for (int i = 0; i < SIDE; ++i)
#pragma unroll
        for (int j = 0; j < SIDE; ++j)
            pv[i * SIDE + j] = __ldg(xp + i * IMG + j);

    const float* wr = ws + tid * SEG;  // stride 25 across lanes: conflict-free
    const float* qr = qs + tid * SEG;

    const float INV_PI = 0.31830988618379067f;
    const float LN2    = 0.69314718055994531f;

    float acc = 0.0f;
#pragma unroll
    for (int k = 0; k < SEG; ++k) {
        float t  = __fmaf_rn(pv[k], wr[k], -qr[k]);   // p*w - q
        float a  = fast_atan(10.0f * t);
        float v  = __fmaf_rn(a, INV_PI, 1.1f);        // 1.1 + atan/pi  (in (0.6,1.6))
        float l2 = __log2f(v);                        // MUFU.LG2
        acc = __fmaf_rn(l2, LN2, acc);                // accumulate natural log
    }
    out[o] = acc;
}

extern "C" void kernel_launch(void* const* d_in, const int* in_sizes, int n_in,
                              void* d_out, int out_size)
{
    const float* x = (const float*)d_in[0];
    const float* w = (const float*)d_in[1];
    const float* q = (const float*)d_in[2];
    float* out = (float*)d_out;

    const int n_out = out_size;       // 1,153,200
    const int n_wq  = in_sizes[1];    // 28,830,000

    const int blocks = (n_out + TPB - 1) / TPB;  // 5149
    dendrite_kernel<<<blocks, TPB>>>(x, w, q, out, n_out, n_wq);
}

// round 2
// speedup vs baseline: 1.4667x; 1.4667x over previous
#include <cuda_runtime.h>
#include <cstdint>

// Dendrite_755914244697 on sm_103a — persistent double-buffered cp.async.bulk pipeline.
//
// out[o] = sum_{k<25} log(1.1 + atan(10*(p[k]*w[o*25+k] - q[o*25+k]))/pi)
// where p[k] is the 5x5 patch of x at the spatial position encoded in o.
//
// w,q are streamed once (230 MB total) -> DRAM-bound; the pipeline keeps the
// HBM stream continuous: thread 0 bulk-copies tile t+G into the free stage
// while all 256 threads compute tile t from the full stage.

#define IMG   128
#define OUTD  124
#define SIDE  5
#define SEG   25
#define TPB   256
#define TILE  256                       // outputs per tile (== TPB)
#define TILE_BYTES (TILE * SEG * 4)     // 25600 B per array per tile
#define STAGE_BYTES (2 * TILE_BYTES)    // w + q
#define SMEM_BYTES (32 + 2 * STAGE_BYTES)  // 2 stages + barriers

__device__ __forceinline__ uint32_t smem_u32(const void* p)
{
    uint32_t a;
    asm("{ .reg .u64 t; cvta.to.shared.u64 t, %1; cvt.u32.u64 %0, t; }"
        : "=r"(a) : "l"(p));
    return a;
}

__device__ __forceinline__ void mbar_init(uint32_t mb, uint32_t count)
{
    asm volatile("mbarrier.init.shared.b64 [%0], %1;" :: "r"(mb), "r"(count) : "memory");
}

__device__ __forceinline__ void mbar_expect_tx(uint32_t mb, uint32_t bytes)
{
    asm volatile("mbarrier.arrive.expect_tx.shared.b64 _, [%0], %1;"
                 :: "r"(mb), "r"(bytes) : "memory");
}

__device__ __forceinline__ void bulk_g2s(uint32_t dst, const void* src,
                                         uint32_t bytes, uint32_t mb)
{
    asm volatile("cp.async.bulk.shared::cta.global.mbarrier::complete_tx::bytes "
                 "[%0], [%1], %2, [%3];"
                 :: "r"(dst), "l"(src), "r"(bytes), "r"(mb) : "memory");
}

__device__ __forceinline__ void mbar_wait(uint32_t mb, uint32_t phase)
{
    uint32_t done;
    asm volatile(
        "{ .reg .pred p;\n"
        "  mbarrier.try_wait.parity.acquire.cta.shared::cta.b64 p, [%1], %2;\n"
        "  selp.b32 %0, 1, 0, p; }"
        : "=r"(done) : "r"(mb), "r"(phase) : "memory");
    while (!done) {
        asm volatile(
            "{ .reg .pred p;\n"
            "  mbarrier.try_wait.parity.acquire.cta.shared::cta.b64 p, [%1], %2, 0x989680;\n"
            "  selp.b32 %0, 1, 0, p; }"
            : "=r"(done) : "r"(mb), "r"(phase) : "memory");
    }
}

__device__ __forceinline__ float fast_atan(float x)
{
    // odd minimax poly on [0,1], |x|>1 via atan(x) = pi/2 - atan(1/x). ~1e-7 abs err.
    float ax = fabsf(x);
    float inv;
    asm("rcp.approx.f32 %0, %1;" : "=f"(inv) : "f"(ax));
    bool  big = ax > 1.0f;
    float z   = big ? inv : ax;
    float s   = z * z;
    float p   =              -0.0040540580f;
    p = __fmaf_rn(p, s,  0.0218612288f);
    p = __fmaf_rn(p, s, -0.0559098861f);
    p = __fmaf_rn(p, s,  0.0964200441f);
    p = __fmaf_rn(p, s, -0.1390853351f);
    p = __fmaf_rn(p, s,  0.1994653599f);
    p = __fmaf_rn(p, s, -0.3332985605f);
    p = __fmaf_rn(p, s,  0.9999993329f);
    float r = p * z;
    if (big) r = 1.5707963268f - r;
    return __uint_as_float((__float_as_uint(r) & 0x7fffffffu) |
                           (__float_as_uint(x) & 0x80000000u));
}

__global__ void __launch_bounds__(TPB, 2)
dendrite_kernel(const float* __restrict__ x,
                const float* __restrict__ w,
                const float* __restrict__ q,
                float*       __restrict__ out,
                int n_out)
{
    extern __shared__ char smem[];
    const uint32_t sb   = smem_u32(smem);
    const uint32_t mb0  = sb;            // two mbarriers at [0,16)
    float* buf = reinterpret_cast<float*>(smem + 32);

    const int tid = threadIdx.x;

    if (tid == 0) {
        mbar_init(mb0,     1);
        mbar_init(mb0 + 8, 1);
        asm volatile("fence.proxy.async.shared::cta;" ::: "memory");
    }
    __syncthreads();

    const int ntiles = (n_out + TILE - 1) / TILE;
    int t = blockIdx.x;
    if (t >= ntiles) return;

    const int G = gridDim.x;

    // issue bulk load of tile `tile` into stage `st`
    auto issue = [&](int st, int tile) {
        const int cnt      = min(TILE, n_out - tile * TILE);
        const uint32_t nb  = (uint32_t)cnt * SEG * 4;   // multiple of 16 for this shape
        const uint32_t mb  = mb0 + st * 8;
        const uint32_t dw  = sb + 32 + st * STAGE_BYTES;
        const uint32_t dq  = dw + TILE_BYTES;
        const size_t   off = (size_t)tile * TILE_BYTES;
        mbar_expect_tx(mb, 2 * nb);
        bulk_g2s(dw, (const char*)w + off, nb, mb);
        bulk_g2s(dq, (const char*)q + off, nb, mb);
    };

    if (tid == 0) issue(0, t);

    int s = 0;
    uint32_t ph[2] = {0u, 0u};

    const float INV_PI = 0.31830988618379067f;
    const float LN2    = 0.69314718055994531f;

    for (; t < ntiles; t += G) {
        const int tn = t + G;
        if (tid == 0 && tn < ntiles) issue(s ^ 1, tn);   // prev-prev buffer is free

        mbar_wait(mb0 + s * 8, ph[s]);
        ph[s] ^= 1u;

        const int o = t * TILE + tid;
        if (o < n_out) {
            // decode o = ((c*124 + oy)*124 + ox)*25 + n
            const int sp = o / 25;
            const int c  = sp / (OUTD * OUTD);
            const int r  = sp - c * (OUTD * OUTD);
            const int oy = r / OUTD;
            const int ox = r - oy * OUTD;

            const float* __restrict__ xp = x + (c * IMG + oy) * IMG + ox;
            float pv[SEG];
#pragma unroll
            for (int i = 0; i < SIDE; ++i)
#pragma unroll
                for (int j = 0; j < SIDE; ++j)
                    pv[i * SIDE + j] = __ldg(xp + i * IMG + j);

            const float* wr = buf + s * (STAGE_BYTES / 4) + tid * SEG;
            const float* qr = wr + TILE_BYTES / 4;

            float acc = 0.0f;
#pragma unroll
            for (int k = 0; k < SEG; ++k) {
                float tt = __fmaf_rn(pv[k], wr[k], -qr[k]);
                float a  = fast_atan(10.0f * tt);
                float v  = __fmaf_rn(a, INV_PI, 1.1f);
                float l2 = __log2f(v);
                acc = __fmaf_rn(l2, LN2, acc);
            }
            out[o] = acc;
        }
        __syncthreads();   // everyone done reading stage s before it is refilled
        s ^= 1;
    }
}

extern "C" void kernel_launch(void* const* d_in, const int* in_sizes, int n_in,
                              void* d_out, int out_size)
{
    const float* x = (const float*)d_in[0];
    const float* w = (const float*)d_in[1];
    const float* q = (const float*)d_in[2];
    float* out = (float*)d_out;

    cudaFuncSetAttribute(dendrite_kernel,
                         cudaFuncAttributeMaxDynamicSharedMemorySize, SMEM_BYTES);

    int sm = 148;
    cudaDeviceGetAttribute(&sm, cudaDevAttrMultiProcessorCount, 0);

    const int n_out  = out_size;                     // 1,153,200
    const int ntiles = (n_out + TILE - 1) / TILE;    // 4505
    int grid = sm * 2;
    if (grid > ntiles) grid = ntiles;

    dendrite_kernel<<<grid, TPB, SMEM_BYTES>>>(x, w, q, out, n_out);
}